// round 1
// baseline (speedup 1.0000x reference)
#include <cuda_runtime.h>
#include <math.h>

#define HIDDEN 1024
#define MEM 32
#define KEY 32
#define VAL 32
#define BATCH 2048
#define TLEN 64
#define BT (BATCH*TLEN)   /* 131072 */
#define NWARMUP 4

/* ---------------- scratch (static device arrays; no allocation) ------------ */
__device__ float g_Q [BT*KEY];
__device__ float g_FK[BT*KEY];
__device__ float g_FV[BT*VAL];
__device__ float g_G [BT];

/* ---------------- Kernel 1: fused projection GEMM (fp32) -------------------
 * out[row, 0:96] = h[row,:] @ Wcat^T (+bias), col 96 = gate logit
 * Wcat rows: 0..31 = W_query, 32..63 = W_fk, 64..95 = W_fv, 96 = W_gate
 * BM=128 rows/block, BK=16, 256 threads, thread microtile 8x6.
 */
#define BM 128
#define BKK 16
#define TM 8
#define TN 6

__global__ __launch_bounds__(256) void proj_kernel(
    const float* __restrict__ h,
    const float* __restrict__ Wg, const float* __restrict__ bg,
    const float* __restrict__ Wq, const float* __restrict__ bq,
    const float* __restrict__ Wk, const float* __restrict__ bk_,
    const float* __restrict__ Wv, const float* __restrict__ bv)
{
    __shared__ float As[BKK][BM+4];    /* k-major, padded stride 132 */
    __shared__ float Bs[BKK][104];     /* cols 0..95 main, 96 = gate */

    const int tid = threadIdx.x;
    const int tx = tid & 15;           /* col group: cols tx*6 .. tx*6+5 */
    const int ty = tid >> 4;           /* row group: rows ty*8 .. ty*8+7 */
    const long r0 = (long)blockIdx.x * BM;

    float acc[TM][TN];
    #pragma unroll
    for (int i = 0; i < TM; i++)
        #pragma unroll
        for (int j = 0; j < TN; j++) acc[i][j] = 0.f;
    float accg = 0.f;

    for (int k0 = 0; k0 < HIDDEN; k0 += BKK) {
        /* load A tile: 128 rows x 16 k = 512 float4 */
        #pragma unroll
        for (int l = 0; l < 2; l++) {
            int i   = tid + l * 256;       /* 0..511 */
            int row = i >> 2;
            int kg  = (i & 3) * 4;
            const float4 v = *(const float4*)(h + (r0 + row) * HIDDEN + k0 + kg);
            As[kg+0][row] = v.x;
            As[kg+1][row] = v.y;
            As[kg+2][row] = v.z;
            As[kg+3][row] = v.w;
        }
        /* load B tile: 97 rows x 16 k = 388 float4 */
        for (int i = tid; i < 97*4; i += 256) {
            int n  = i >> 2;
            int kg = (i & 3) * 4;
            const float* src;
            if      (n < 32) src = Wq + n      * HIDDEN;
            else if (n < 64) src = Wk + (n-32) * HIDDEN;
            else if (n < 96) src = Wv + (n-64) * HIDDEN;
            else             src = Wg;
            const float4 v = *(const float4*)(src + k0 + kg);
            Bs[kg+0][n] = v.x;
            Bs[kg+1][n] = v.y;
            Bs[kg+2][n] = v.z;
            Bs[kg+3][n] = v.w;
        }
        __syncthreads();

        #pragma unroll
        for (int kk = 0; kk < BKK; kk++) {
            float a[TM], b[TN];
            #pragma unroll
            for (int i = 0; i < TM; i++) a[i] = As[kk][ty*TM + i];
            #pragma unroll
            for (int j = 0; j < TN; j++) b[j] = Bs[kk][tx*TN + j];
            #pragma unroll
            for (int i = 0; i < TM; i++)
                #pragma unroll
                for (int j = 0; j < TN; j++)
                    acc[i][j] = fmaf(a[i], b[j], acc[i][j]);
            /* fused gate column: warps 0..3, one row per thread */
            if (tid < 128) accg = fmaf(As[kk][tid], Bs[kk][96], accg);
        }
        __syncthreads();
    }

    /* epilogue */
    #pragma unroll
    for (int i = 0; i < TM; i++) {
        long row = r0 + ty*TM + i;
        #pragma unroll
        for (int j = 0; j < TN; j++) {
            int n = tx*TN + j;
            float v = acc[i][j];
            if      (n < 32) g_Q [row*KEY + n]      = v + bq [n];
            else if (n < 64) g_FK[row*KEY + (n-32)] = v + bk_[n-32];
            else             g_FV[row*VAL + (n-64)] = v + bv [n-64];
        }
    }
    if (tid < 128) g_G[r0 + tid] = accg + bg[0];
}

/* ---------------- Kernel 2: recurrence, one warp per batch ----------------- */
#define NW 2   /* warps (batches) per block */

__global__ __launch_bounds__(32*NW) void rnn_kernel(float* __restrict__ es,
                                                    float* __restrict__ ps)
{
    __shared__ float Vs [NW][MEM][VAL+1];
    __shared__ float qs [NW][KEY];
    __shared__ float fks[NW][KEY];
    __shared__ float fvs[NW][VAL];
    __shared__ float ats[NW][MEM];

    const int w    = threadIdx.x >> 5;
    const int lane = threadIdx.x & 31;
    const int b    = blockIdx.x * NW + w;
    const unsigned FULL = 0xffffffffu;
    const float scale = 0.17677669529663688f;   /* 1/sqrt(32) */

    /* state: lane = memory slot */
    float K[KEY];
    #pragma unroll
    for (int j = 0; j < KEY; j++) { K[j] = 0.f; Vs[w][lane][j] = 0.f; }
    float Tf = 0.f, msk = 0.f;
    __syncwarp();

    for (int t = 0; t < TLEN; t++) {
        const long row = (long)b * TLEN + t;

        float qv  = g_Q [row*KEY + lane];
        float fkv = g_FK[row*KEY + lane];
        float fvv = g_FV[row*VAL + lane];
        qs [w][lane] = qv;
        fks[w][lane] = fkv;
        fvs[w][lane] = fvv;
        __syncwarp();

        /* logits[m] = (K[m,:] . q) * scale, masked */
        float lg = 0.f;
        #pragma unroll
        for (int j = 0; j < KEY; j++) lg = fmaf(K[j], qs[w][j], lg);
        lg *= scale;
        float lm = fmaf(1.0f - msk, -1e9f, lg);   /* exact 0/-1e9 product */

        /* softmax across warp */
        float mx = lm;
        #pragma unroll
        for (int off = 16; off; off >>= 1)
            mx = fmaxf(mx, __shfl_xor_sync(FULL, mx, off));
        float ex = expf(lm - mx);
        float sm = ex;
        #pragma unroll
        for (int off = 16; off; off >>= 1)
            sm += __shfl_xor_sync(FULL, sm, off);
        float attn = ex / sm;
        ats[w][lane] = attn;

        /* argmax(attn), first index on ties */
        float bvv = attn; int bii = lane;
        #pragma unroll
        for (int off = 16; off; off >>= 1) {
            float ov = __shfl_down_sync(FULL, bvv, off);
            int   oi = __shfl_down_sync(FULL, bii, off);
            if (ov > bvv || (ov == bvv && oi < bii)) { bvv = ov; bii = oi; }
        }
        int amax = __shfl_sync(FULL, bii, 0);
        __syncwarp();

        /* retrv[v] = sum_m attn[m] * V[m][v]   (lane = v) */
        float r = 0.f;
        #pragma unroll
        for (int m = 0; m < MEM; m++)
            r = fmaf(ats[w][m], Vs[w][m][lane], r);

        /* gate logic: gate<0.5 <=> logit<0 (exact 0/1 factors) */
        float gx = g_G[row];
        unsigned bal = __ballot_sync(FULL, msk != 0.f);
        bool empty = (bal == 0u);
        bool warm  = (t < NWARMUP);
        float p = 1.f / (1.f + expf(-gx));
        float gate = (empty || warm) ? 0.f : p;
        bool wr = empty || warm || (gx < 0.f);

        float om = 1.0f - gate;
        float e  = gate * r + om * fvv;
        es[row*VAL + lane] = e;
        if (lane == 0) ps[row] = p;

        /* evict = argmin(Tf + mask*0.001), first index on ties */
        float evv = Tf + msk * 0.001f;
        float bmv = evv; int bmi = lane;
        #pragma unroll
        for (int off = 16; off; off >>= 1) {
            float ov = __shfl_down_sync(FULL, bmv, off);
            int   oi = __shfl_down_sync(FULL, bmi, off);
            if (ov < bmv || (ov == bmv && oi < bmi)) { bmv = ov; bmi = oi; }
        }
        int evict = __shfl_sync(FULL, bmi, 0);

        /* write: K/V/mask update (exact: w3 is one-hot 0/1) */
        if (wr && lane == evict) {
            msk = 1.f;
            #pragma unroll
            for (int j = 0; j < KEY; j++) {
                K[j] = fks[w][j];
                Vs[w][lane][j] = fvs[w][j];
            }
        }
        /* Tf update — mirror JAX expression exactly:
           A = Tf*DECAY;  T_new = A + bump*(1-A) */
        int bslot = wr ? evict : amax;
        float A = Tf * 0.85f;
        Tf = (lane == bslot) ? (A + (1.0f - A)) : A;
        __syncwarp();
    }
}

/* ---------------- launch ---------------------------------------------------- */
extern "C" void kernel_launch(void* const* d_in, const int* in_sizes, int n_in,
                              void* d_out, int out_size)
{
    const float* h  = (const float*)d_in[0];
    const float* Wg = (const float*)d_in[1];
    const float* bg = (const float*)d_in[2];
    const float* Wq = (const float*)d_in[3];
    const float* bq = (const float*)d_in[4];
    const float* Wk = (const float*)d_in[5];
    const float* bk = (const float*)d_in[6];
    const float* Wv = (const float*)d_in[7];
    const float* bv = (const float*)d_in[8];

    float* es = (float*)d_out;
    float* ps = es + ((long)out_size - BT);   /* es first, ps after */

    proj_kernel<<<BT/BM, 256>>>(h, Wg, bg, Wq, bq, Wk, bk, Wv, bv);
    rnn_kernel<<<BATCH/NW, 32*NW>>>(es, ps);
}

// round 3
// speedup vs baseline: 1.3790x; 1.3790x over previous
#include <cuda_runtime.h>
#include <math.h>
#include <stdint.h>

#define HIDDEN 1024
#define MEM 32
#define KEY 32
#define VAL 32
#define BATCH 2048
#define TLEN 64
#define BT (BATCH*TLEN)   /* 131072 */
#define NWARMUP 4

/* ---------------- proj tiling --------------------------------------------- */
#define BMp 128            /* rows per CTA */
#define BNp 96             /* proj cols (gate handled separately) */
#define BKp 16             /* k per chunk */
#define NCHUNKS (HIDDEN/BKp)   /* 64 */
/* 128 threads: colgrp = tid&15 (6 cols each), rowgrp = tid>>4 (16 rows each) */

/* ---------------- scratch (static device arrays; no allocation) ----------- */
__device__ float  g_Q [BT*KEY];
__device__ float  g_FK[BT*KEY];
__device__ float  g_FV[BT*VAL];
__device__ float  g_G [BT];
/* B weights, duplicated pairs, interleaved: [chunk][kk][j*16+colgrp] */
__device__ float2 g_Bdup[NCHUNKS][BKp][BNp];

/* ---------------- helpers -------------------------------------------------- */
__device__ __forceinline__ void ffma2(unsigned long long& d,
                                      unsigned long long a,
                                      unsigned long long b) {
    asm("fma.rn.f32x2 %0, %1, %2, %0;" : "+l"(d) : "l"(a), "l"(b));
}
__device__ __forceinline__ float f2lo(unsigned long long v) {
    return __uint_as_float((unsigned)(v & 0xffffffffu));
}
__device__ __forceinline__ float f2hi(unsigned long long v) {
    return __uint_as_float((unsigned)(v >> 32));
}

/* ---------------- prep: duplicate + interleave weights --------------------- */
__global__ __launch_bounds__(256) void prep_kernel(
    const float* __restrict__ Wq, const float* __restrict__ Wk,
    const float* __restrict__ Wv)
{
    int idx = blockIdx.x * 256 + threadIdx.x;    /* 64*16*96 = 98304 */
    int c   = idx / (BKp * BNp);
    int rem = idx % (BKp * BNp);
    int kk  = rem / BNp;
    int col = rem % BNp;
    int k   = c * BKp + kk;

    float b;
    if      (col < 32) b = Wq[col * HIDDEN + k];
    else if (col < 64) b = Wk[(col - 32) * HIDDEN + k];
    else               b = Wv[(col - 64) * HIDDEN + k];

    int colgrp = col / 6;
    int j      = col % 6;
    g_Bdup[c][kk][j * 16 + colgrp] = make_float2(b, b);
}

/* ---------------- proj kernel: FFMA2 (f32x2) GEMM -------------------------- */
__global__ __launch_bounds__(128) void proj_kernel(
    const float* __restrict__ hmat,
    const float* __restrict__ Wg, const float* __restrict__ bg,
    const float* __restrict__ bq, const float* __restrict__ bk_,
    const float* __restrict__ bv)
{
    __shared__ float  As[2][BKp][BMp + 2];   /* k-major, stride 130 (even) */
    __shared__ float2 Bs[2][BKp][BNp];       /* dup pairs, interleaved */
    __shared__ float  Gs[2][BKp];

    const int tid    = threadIdx.x;
    const int colgrp = tid & 15;
    const int rowgrp = tid >> 4;
    const long r0    = (long)blockIdx.x * BMp;

    unsigned long long acc[8][6];
    #pragma unroll
    for (int i = 0; i < 8; i++)
        #pragma unroll
        for (int j = 0; j < 6; j++) acc[i][j] = 0ull;
    float accg = 0.f;

    /* prologue: load chunk 0 into regs, stage 0 */
    float4 av[4];
    float4 bvv[6];
    float  gv;
    {
        const float* arow = hmat + (r0 + tid) * HIDDEN;
        #pragma unroll
        for (int q = 0; q < 4; q++) av[q] = *(const float4*)(arow + q * 4);
        const float4* bsrc = (const float4*)&g_Bdup[0][0][0];
        #pragma unroll
        for (int q = 0; q < 6; q++) bvv[q] = bsrc[tid + 128 * q];
        gv = (tid < BKp) ? Wg[tid] : 0.f;
    }
    /* STS chunk 0 -> stage 0 */
    {
        #pragma unroll
        for (int q = 0; q < 4; q++) {
            As[0][q*4+0][tid] = av[q].x;
            As[0][q*4+1][tid] = av[q].y;
            As[0][q*4+2][tid] = av[q].z;
            As[0][q*4+3][tid] = av[q].w;
        }
        float4* bdst = (float4*)&Bs[0][0][0];
        #pragma unroll
        for (int q = 0; q < 6; q++) bdst[tid + 128 * q] = bvv[q];
        if (tid < BKp) Gs[0][tid] = gv;
    }
    __syncthreads();

    for (int c = 0; c < NCHUNKS; c++) {
        const int s = c & 1;

        /* prefetch chunk c+1 into regs */
        if (c + 1 < NCHUNKS) {
            const int k0n = (c + 1) * BKp;
            const float* arow = hmat + (r0 + tid) * HIDDEN + k0n;
            #pragma unroll
            for (int q = 0; q < 4; q++) av[q] = *(const float4*)(arow + q * 4);
            const float4* bsrc = (const float4*)&g_Bdup[c + 1][0][0];
            #pragma unroll
            for (int q = 0; q < 6; q++) bvv[q] = bsrc[tid + 128 * q];
            gv = (tid < BKp) ? Wg[k0n + tid] : 0.f;
        }

        /* compute 16 kk from stage s */
        #pragma unroll
        for (int kk = 0; kk < BKp; kk++) {
            unsigned long long a[8], b[6];
            #pragma unroll
            for (int i = 0; i < 8; i++)
                a[i] = *(const unsigned long long*)&As[s][kk][rowgrp * 16 + 2 * i];
            #pragma unroll
            for (int j = 0; j < 6; j++)
                b[j] = *(const unsigned long long*)&Bs[s][kk][j * 16 + colgrp];
            #pragma unroll
            for (int i = 0; i < 8; i++)
                #pragma unroll
                for (int j = 0; j < 6; j++)
                    ffma2(acc[i][j], a[i], b[j]);
            accg = fmaf(As[s][kk][tid], Gs[s][kk], accg);
        }

        /* store prefetched chunk to other stage */
        if (c + 1 < NCHUNKS) {
            const int sn = s ^ 1;
            #pragma unroll
            for (int q = 0; q < 4; q++) {
                As[sn][q*4+0][tid] = av[q].x;
                As[sn][q*4+1][tid] = av[q].y;
                As[sn][q*4+2][tid] = av[q].z;
                As[sn][q*4+3][tid] = av[q].w;
            }
            float4* bdst = (float4*)&Bs[sn][0][0];
            #pragma unroll
            for (int q = 0; q < 6; q++) bdst[tid + 128 * q] = bvv[q];
            if (tid < BKp) Gs[sn][tid] = gv;
        }
        __syncthreads();
    }

    /* epilogue */
    const int C = colgrp * 6;
    float bias[6];
    #pragma unroll
    for (int j = 0; j < 6; j++) {
        int col = C + j;
        bias[j] = (col < 32) ? bq[col] : (col < 64) ? bk_[col - 32] : bv[col - 64];
    }
    #pragma unroll
    for (int i = 0; i < 8; i++) {
        long row0 = r0 + rowgrp * 16 + 2 * i;
        float v0[6], v1[6];
        #pragma unroll
        for (int j = 0; j < 6; j++) {
            v0[j] = f2lo(acc[i][j]) + bias[j];
            v1[j] = f2hi(acc[i][j]) + bias[j];
        }
        #pragma unroll
        for (int jj = 0; jj < 6; jj += 2) {
            int col = C + jj;
            float* dst;
            int cc;
            if      (col < 32) { dst = g_Q;  cc = col; }
            else if (col < 64) { dst = g_FK; cc = col - 32; }
            else               { dst = g_FV; cc = col - 64; }
            *(float2*)(dst + row0 * 32 + cc)       = make_float2(v0[jj], v0[jj+1]);
            *(float2*)(dst + (row0 + 1) * 32 + cc) = make_float2(v1[jj], v1[jj+1]);
        }
    }
    g_G[r0 + tid] = accg + bg[0];
}

/* ---------------- Kernel 2: recurrence, one warp per batch ----------------- */
#define NW 2

__global__ __launch_bounds__(32*NW) void rnn_kernel(float* __restrict__ es,
                                                    float* __restrict__ ps)
{
    __shared__ float Vs [NW][MEM][VAL+1];
    __shared__ float qs [NW][KEY];
    __shared__ float fks[NW][KEY];
    __shared__ float fvs[NW][VAL];
    __shared__ float ats[NW][MEM];

    const int w    = threadIdx.x >> 5;
    const int lane = threadIdx.x & 31;
    const int b    = blockIdx.x * NW + w;
    const unsigned FULL = 0xffffffffu;
    const float scale = 0.17677669529663688f;

    float K[KEY];
    #pragma unroll
    for (int j = 0; j < KEY; j++) { K[j] = 0.f; Vs[w][lane][j] = 0.f; }
    float Tf = 0.f, msk = 0.f;
    __syncwarp();

    const long row0 = (long)b * TLEN;
    float qv  = g_Q [row0*KEY + lane];
    float fkv = g_FK[row0*KEY + lane];
    float fvv = g_FV[row0*VAL + lane];
    float gx  = g_G [row0];

    for (int t = 0; t < TLEN; t++) {
        const long row  = row0 + t;
        const long nrow = (t < TLEN-1) ? row + 1 : row;

        float nq  = g_Q [nrow*KEY + lane];
        float nfk = g_FK[nrow*KEY + lane];
        float nfv = g_FV[nrow*VAL + lane];
        float ngx = g_G [nrow];

        qs [w][lane] = qv;
        fks[w][lane] = fkv;
        fvs[w][lane] = fvv;
        __syncwarp();

        float lg = 0.f;
        #pragma unroll
        for (int j = 0; j < KEY; j++) lg = fmaf(K[j], qs[w][j], lg);
        lg *= scale;
        float lm = fmaf(1.0f - msk, -1e9f, lg);

        float mx = lm;
        #pragma unroll
        for (int off = 16; off; off >>= 1)
            mx = fmaxf(mx, __shfl_xor_sync(FULL, mx, off));
        float ex = expf(lm - mx);
        float sm = ex;
        #pragma unroll
        for (int off = 16; off; off >>= 1)
            sm += __shfl_xor_sync(FULL, sm, off);
        float attn = ex / sm;
        ats[w][lane] = attn;

        float bvv = attn; int bii = lane;
        #pragma unroll
        for (int off = 16; off; off >>= 1) {
            float ov = __shfl_down_sync(FULL, bvv, off);
            int   oi = __shfl_down_sync(FULL, bii, off);
            if (ov > bvv || (ov == bvv && oi < bii)) { bvv = ov; bii = oi; }
        }
        int amax = __shfl_sync(FULL, bii, 0);
        __syncwarp();

        float r = 0.f;
        #pragma unroll
        for (int m = 0; m < MEM; m++)
            r = fmaf(ats[w][m], Vs[w][m][lane], r);

        unsigned bal = __ballot_sync(FULL, msk != 0.f);
        bool empty = (bal == 0u);
        bool warm  = (t < NWARMUP);
        float p = 1.f / (1.f + expf(-gx));
        float gate = (empty || warm) ? 0.f : p;
        bool wr = empty || warm || (gx < 0.f);

        float om = 1.0f - gate;
        float e  = gate * r + om * fvv;
        es[row*VAL + lane] = e;
        if (lane == 0) ps[row] = p;

        float evv = Tf + msk * 0.001f;
        float bmv = evv; int bmi = lane;
        #pragma unroll
        for (int off = 16; off; off >>= 1) {
            float ov = __shfl_down_sync(FULL, bmv, off);
            int   oi = __shfl_down_sync(FULL, bmi, off);
            if (ov < bmv || (ov == bmv && oi < bmi)) { bmv = ov; bmi = oi; }
        }
        int evict = __shfl_sync(FULL, bmi, 0);

        if (wr && lane == evict) {
            msk = 1.f;
            #pragma unroll
            for (int j = 0; j < KEY; j++) {
                K[j] = fks[w][j];
                Vs[w][lane][j] = fvs[w][j];
            }
        }
        int bslot = wr ? evict : amax;
        float A = Tf * 0.85f;
        Tf = (lane == bslot) ? (A + (1.0f - A)) : A;
        __syncwarp();

        qv = nq; fkv = nfk; fvv = nfv; gx = ngx;
    }
}

/* ---------------- launch ---------------------------------------------------- */
extern "C" void kernel_launch(void* const* d_in, const int* in_sizes, int n_in,
                              void* d_out, int out_size)
{
    const float* h  = (const float*)d_in[0];
    const float* Wg = (const float*)d_in[1];
    const float* bg = (const float*)d_in[2];
    const float* Wq = (const float*)d_in[3];
    const float* bq = (const float*)d_in[4];
    const float* Wk = (const float*)d_in[5];
    const float* bk = (const float*)d_in[6];
    const float* Wv = (const float*)d_in[7];
    const float* bv = (const float*)d_in[8];

    float* es = (float*)d_out;
    float* ps = es + ((long)out_size - BT);

    prep_kernel<<<(NCHUNKS*BKp*BNp)/256, 256>>>(Wq, Wk, Wv);
    proj_kernel<<<BT/BMp, 128>>>(h, Wg, bg, bq, bk, bv);
    rnn_kernel<<<BATCH/NW, 32*NW>>>(es, ps);
}

// round 4
// speedup vs baseline: 1.4201x; 1.0298x over previous
#include <cuda_runtime.h>
#include <math.h>
#include <stdint.h>

#define HIDDEN 1024
#define MEM 32
#define KEY 32
#define VAL 32
#define BATCH 2048
#define TLEN 64
#define BT (BATCH*TLEN)   /* 131072 */
#define NWARMUP 4

/* ---------------- proj tiling --------------------------------------------- */
#define BMp 128            /* rows per CTA */
#define BNp 96             /* proj cols (gate handled separately) */
#define BKp 16             /* k per chunk */
#define NCHUNKS (HIDDEN/BKp)   /* 64 */
/* 128 threads: colgrp = tid&15 (6 cols each), rowgrp = tid>>4 (16 rows each) */

/* ---------------- scratch (static device arrays; no allocation) ----------- */
__device__ float g_Q [BT*KEY];
__device__ float g_FK[BT*KEY];
__device__ float g_FV[BT*VAL];
__device__ float g_G [BT];
/* B weights, scalar, interleaved: [chunk][kk][j*16+colgrp] */
__device__ float g_B[NCHUNKS][BKp][BNp];

/* ---------------- helpers -------------------------------------------------- */
__device__ __forceinline__ void ffma2(unsigned long long& d,
                                      unsigned long long a,
                                      unsigned long long b) {
    asm("fma.rn.f32x2 %0, %1, %2, %0;" : "+l"(d) : "l"(a), "l"(b));
}
__device__ __forceinline__ unsigned long long dup2(float b) {
    unsigned long long r;
    unsigned u = __float_as_uint(b);
    asm("mov.b64 %0, {%1, %1};" : "=l"(r) : "r"(u));
    return r;
}
__device__ __forceinline__ float f2lo(unsigned long long v) {
    return __uint_as_float((unsigned)(v & 0xffffffffu));
}
__device__ __forceinline__ float f2hi(unsigned long long v) {
    return __uint_as_float((unsigned)(v >> 32));
}
__device__ __forceinline__ unsigned redux_umax(unsigned v) {
    unsigned r;
    asm("redux.sync.max.u32 %0, %1, 0xffffffff;" : "=r"(r) : "r"(v));
    return r;
}
__device__ __forceinline__ unsigned redux_umin(unsigned v) {
    unsigned r;
    asm("redux.sync.min.u32 %0, %1, 0xffffffff;" : "=r"(r) : "r"(v));
    return r;
}

/* ---------------- prep: interleave weights --------------------------------- */
__global__ __launch_bounds__(256) void prep_kernel(
    const float* __restrict__ Wq, const float* __restrict__ Wk,
    const float* __restrict__ Wv)
{
    int idx = blockIdx.x * 256 + threadIdx.x;    /* 64*16*96 = 98304 */
    int c   = idx / (BKp * BNp);
    int rem = idx % (BKp * BNp);
    int kk  = rem / BNp;
    int col = rem % BNp;
    int k   = c * BKp + kk;

    float b;
    if      (col < 32) b = Wq[col * HIDDEN + k];
    else if (col < 64) b = Wk[(col - 32) * HIDDEN + k];
    else               b = Wv[(col - 64) * HIDDEN + k];

    int colgrp = col / 6;
    int j      = col % 6;
    g_B[c][kk][j * 16 + colgrp] = b;
}

/* ---------------- proj kernel: FFMA2 (f32x2) GEMM -------------------------- */
__global__ __launch_bounds__(128) void proj_kernel(
    const float* __restrict__ hmat,
    const float* __restrict__ Wg, const float* __restrict__ bg,
    const float* __restrict__ bq, const float* __restrict__ bk_,
    const float* __restrict__ bv)
{
    __shared__ float As[2][BKp][BMp + 2];   /* k-major, stride 130 (even) */
    __shared__ float Bs[2][BKp][BNp];       /* scalar, interleaved */
    __shared__ float Gs[2][BKp];

    const int tid    = threadIdx.x;
    const int colgrp = tid & 15;
    const int rowgrp = tid >> 4;
    const long r0    = (long)blockIdx.x * BMp;

    unsigned long long acc[8][6];
    #pragma unroll
    for (int i = 0; i < 8; i++)
        #pragma unroll
        for (int j = 0; j < 6; j++) acc[i][j] = 0ull;
    float accg = 0.f;

    /* prologue: load chunk 0 into regs */
    float4 av[4];
    float4 bvv[3];          /* 16*96 floats / 128 thr = 3 float4 each */
    float  gv;
    {
        const float* arow = hmat + (r0 + tid) * HIDDEN;
        #pragma unroll
        for (int q = 0; q < 4; q++) av[q] = *(const float4*)(arow + q * 4);
        const float4* bsrc = (const float4*)&g_B[0][0][0];
        #pragma unroll
        for (int q = 0; q < 3; q++) bvv[q] = bsrc[tid + 128 * q];
        gv = (tid < BKp) ? Wg[tid] : 0.f;
    }
    /* STS chunk 0 -> stage 0 */
    {
        #pragma unroll
        for (int q = 0; q < 4; q++) {
            As[0][q*4+0][tid] = av[q].x;
            As[0][q*4+1][tid] = av[q].y;
            As[0][q*4+2][tid] = av[q].z;
            As[0][q*4+3][tid] = av[q].w;
        }
        float4* bdst = (float4*)&Bs[0][0][0];
        #pragma unroll
        for (int q = 0; q < 3; q++) bdst[tid + 128 * q] = bvv[q];
        if (tid < BKp) Gs[0][tid] = gv;
    }
    __syncthreads();

    for (int c = 0; c < NCHUNKS; c++) {
        const int s = c & 1;

        /* prefetch chunk c+1 into regs */
        if (c + 1 < NCHUNKS) {
            const int k0n = (c + 1) * BKp;
            const float* arow = hmat + (r0 + tid) * HIDDEN + k0n;
            #pragma unroll
            for (int q = 0; q < 4; q++) av[q] = *(const float4*)(arow + q * 4);
            const float4* bsrc = (const float4*)&g_B[c + 1][0][0];
            #pragma unroll
            for (int q = 0; q < 3; q++) bvv[q] = bsrc[tid + 128 * q];
            gv = (tid < BKp) ? Wg[k0n + tid] : 0.f;
        }

        /* compute 16 kk from stage s */
        #pragma unroll
        for (int kk = 0; kk < BKp; kk++) {
            unsigned long long a[8], b[6];
            #pragma unroll
            for (int i = 0; i < 8; i++)
                a[i] = *(const unsigned long long*)&As[s][kk][rowgrp * 16 + 2 * i];
            #pragma unroll
            for (int j = 0; j < 6; j++)
                b[j] = dup2(Bs[s][kk][j * 16 + colgrp]);
            #pragma unroll
            for (int i = 0; i < 8; i++)
                #pragma unroll
                for (int j = 0; j < 6; j++)
                    ffma2(acc[i][j], a[i], b[j]);
            accg = fmaf(As[s][kk][tid], Gs[s][kk], accg);
        }

        /* store prefetched chunk to other stage */
        if (c + 1 < NCHUNKS) {
            const int sn = s ^ 1;
            #pragma unroll
            for (int q = 0; q < 4; q++) {
                As[sn][q*4+0][tid] = av[q].x;
                As[sn][q*4+1][tid] = av[q].y;
                As[sn][q*4+2][tid] = av[q].z;
                As[sn][q*4+3][tid] = av[q].w;
            }
            float4* bdst = (float4*)&Bs[sn][0][0];
            #pragma unroll
            for (int q = 0; q < 3; q++) bdst[tid + 128 * q] = bvv[q];
            if (tid < BKp) Gs[sn][tid] = gv;
        }
        __syncthreads();
    }

    /* epilogue */
    const int C = colgrp * 6;
    float bias[6];
    #pragma unroll
    for (int j = 0; j < 6; j++) {
        int col = C + j;
        bias[j] = (col < 32) ? bq[col] : (col < 64) ? bk_[col - 32] : bv[col - 64];
    }
    #pragma unroll
    for (int i = 0; i < 8; i++) {
        long row0 = r0 + rowgrp * 16 + 2 * i;
        float v0[6], v1[6];
        #pragma unroll
        for (int j = 0; j < 6; j++) {
            v0[j] = f2lo(acc[i][j]) + bias[j];
            v1[j] = f2hi(acc[i][j]) + bias[j];
        }
        #pragma unroll
        for (int jj = 0; jj < 6; jj += 2) {
            int col = C + jj;
            float* dst;
            int cc;
            if      (col < 32) { dst = g_Q;  cc = col; }
            else if (col < 64) { dst = g_FK; cc = col - 32; }
            else               { dst = g_FV; cc = col - 64; }
            *(float2*)(dst + row0 * 32 + cc)       = make_float2(v0[jj], v0[jj+1]);
            *(float2*)(dst + (row0 + 1) * 32 + cc) = make_float2(v1[jj], v1[jj+1]);
        }
    }
    g_G[r0 + tid] = accg + bg[0];
}

/* ---------------- Kernel 2: recurrence, one warp per batch ----------------- */
#define NW 2

__global__ __launch_bounds__(32*NW) void rnn_kernel(float* __restrict__ es,
                                                    float* __restrict__ ps)
{
    __shared__ float Vs [NW][MEM][VAL+1];
    __shared__ float qs [NW][KEY];
    __shared__ float fks[NW][KEY];
    __shared__ float fvs[NW][VAL];
    __shared__ float ats[NW][MEM];

    const int w    = threadIdx.x >> 5;
    const int lane = threadIdx.x & 31;
    const int b    = blockIdx.x * NW + w;
    const unsigned FULL = 0xffffffffu;
    const float scale = 0.17677669529663688f;

    float K[KEY];
    #pragma unroll
    for (int j = 0; j < KEY; j++) { K[j] = 0.f; Vs[w][lane][j] = 0.f; }
    float Tf = 0.f, msk = 0.f;
    __syncwarp();

    const long row0 = (long)b * TLEN;
    float qv  = g_Q [row0*KEY + lane];
    float fkv = g_FK[row0*KEY + lane];
    float fvv = g_FV[row0*VAL + lane];
    float gx  = g_G [row0];

    for (int t = 0; t < TLEN; t++) {
        const long row  = row0 + t;
        const long nrow = (t < TLEN-1) ? row + 1 : row;

        /* prefetch next step */
        float nq  = g_Q [nrow*KEY + lane];
        float nfk = g_FK[nrow*KEY + lane];
        float nfv = g_FV[nrow*VAL + lane];
        float ngx = g_G [nrow];

        qs [w][lane] = qv;
        fks[w][lane] = fkv;
        fvs[w][lane] = fvv;
        __syncwarp();

        /* logits[m] = (K[m,:] . q) * scale, masked */
        float lg = 0.f;
        #pragma unroll
        for (int j = 0; j < KEY; j++) lg = fmaf(K[j], qs[w][j], lg);
        lg *= scale;
        float lm = fmaf(1.0f - msk, -1e9f, lg);

        /* max via redux on order-preserving uint key (handles negatives) */
        unsigned ub  = __float_as_uint(lm);
        unsigned key = ub ^ ((unsigned)((int)ub >> 31) | 0x80000000u);
        unsigned km  = redux_umax(key);
        unsigned mb  = (km & 0x80000000u) ? (km ^ 0x80000000u) : ~km;
        float mx = __uint_as_float(mb);

        float ex = expf(lm - mx);
        float sm = ex;
        #pragma unroll
        for (int off = 16; off; off >>= 1)
            sm += __shfl_xor_sync(FULL, sm, off);
        float attn = ex / sm;
        ats[w][lane] = attn;

        /* argmax(attn): attn >= 0 so uint compare is exact; ffs = first index */
        unsigned ab = __float_as_uint(attn);
        unsigned am = redux_umax(ab);
        int amax = __ffs(__ballot_sync(FULL, ab == am)) - 1;
        __syncwarp();

        /* retrv[v] = sum_m attn[m] * V[m][v]   (lane = v) */
        float r = 0.f;
        #pragma unroll
        for (int m = 0; m < MEM; m++)
            r = fmaf(ats[w][m], Vs[w][m][lane], r);

        unsigned bal = __ballot_sync(FULL, msk != 0.f);
        bool empty = (bal == 0u);
        bool warm  = (t < NWARMUP);
        float p = 1.f / (1.f + expf(-gx));
        float gate = (empty || warm) ? 0.f : p;
        bool wr = empty || warm || (gx < 0.f);

        float om = 1.0f - gate;
        float e  = gate * r + om * fvv;
        es[row*VAL + lane] = e;
        if (lane == 0) ps[row] = p;

        /* evict = argmin(Tf + mask*0.001): evv >= 0, uint compare exact */
        float evv = Tf + msk * 0.001f;
        unsigned eb = __float_as_uint(evv);
        unsigned em = redux_umin(eb);
        int evict = __ffs(__ballot_sync(FULL, eb == em)) - 1;

        if (wr && lane == evict) {
            msk = 1.f;
            #pragma unroll
            for (int j = 0; j < KEY; j++) {
                K[j] = fks[w][j];
                Vs[w][lane][j] = fvs[w][j];
            }
        }
        int bslot = wr ? evict : amax;
        float A = Tf * 0.85f;
        Tf = (lane == bslot) ? (A + (1.0f - A)) : A;
        __syncwarp();

        qv = nq; fkv = nfk; fvv = nfv; gx = ngx;
    }
}

/* ---------------- launch ---------------------------------------------------- */
extern "C" void kernel_launch(void* const* d_in, const int* in_sizes, int n_in,
                              void* d_out, int out_size)
{
    const float* h  = (const float*)d_in[0];
    const float* Wg = (const float*)d_in[1];
    const float* bg = (const float*)d_in[2];
    const float* Wq = (const float*)d_in[3];
    const float* bq = (const float*)d_in[4];
    const float* Wk = (const float*)d_in[5];
    const float* bk = (const float*)d_in[6];
    const float* Wv = (const float*)d_in[7];
    const float* bv = (const float*)d_in[8];

    float* es = (float*)d_out;
    float* ps = es + ((long)out_size - BT);

    prep_kernel<<<(NCHUNKS*BKp*BNp)/256, 256>>>(Wq, Wk, Wv);
    proj_kernel<<<BT/BMp, 128>>>(h, Wg, bg, bq, bk, bv);
    rnn_kernel<<<BATCH/NW, 32*NW>>>(es, ps);
}

// round 5
// speedup vs baseline: 1.4980x; 1.0548x over previous
#include <cuda_runtime.h>
#include <math.h>
#include <stdint.h>

#define HIDDEN 1024
#define MEM 32
#define KEY 32
#define VAL 32
#define BATCH 2048
#define TLEN 64
#define BT (BATCH*TLEN)   /* 131072 */
#define NWARMUP 4

/* ---------------- proj tiling --------------------------------------------- */
#define BMp 128            /* rows per CTA */
#define BNp 96             /* proj cols (gate handled separately) */
#define BKp 16             /* k per chunk */
#define NCHUNKS (HIDDEN/BKp)   /* 64 */
/* 256 threads: colgrp = tid&15 (6 cols each), rowgrp = tid>>4 (8 rows each) */

/* ---------------- scratch (static device arrays; no allocation) ----------- */
__device__ float g_Q [BT*KEY];
__device__ float g_FK[BT*KEY];
__device__ float g_FV[BT*VAL];
__device__ float g_G [BT];
/* B weights, scalar, interleaved: [chunk][kk][j*16+colgrp] */
__device__ float g_B[NCHUNKS][BKp][BNp];

/* ---------------- helpers -------------------------------------------------- */
__device__ __forceinline__ void ffma2(unsigned long long& d,
                                      unsigned long long a,
                                      unsigned long long b) {
    asm("fma.rn.f32x2 %0, %1, %2, %0;" : "+l"(d) : "l"(a), "l"(b));
}
__device__ __forceinline__ unsigned long long dup2(float b) {
    unsigned long long r;
    unsigned u = __float_as_uint(b);
    asm("mov.b64 %0, {%1, %1};" : "=l"(r) : "r"(u));
    return r;
}
__device__ __forceinline__ float f2lo(unsigned long long v) {
    return __uint_as_float((unsigned)(v & 0xffffffffu));
}
__device__ __forceinline__ float f2hi(unsigned long long v) {
    return __uint_as_float((unsigned)(v >> 32));
}
__device__ __forceinline__ unsigned redux_umax(unsigned v) {
    unsigned r;
    asm("redux.sync.max.u32 %0, %1, 0xffffffff;" : "=r"(r) : "r"(v));
    return r;
}
__device__ __forceinline__ unsigned redux_umin(unsigned v) {
    unsigned r;
    asm("redux.sync.min.u32 %0, %1, 0xffffffff;" : "=r"(r) : "r"(v));
    return r;
}

/* ---------------- prep: interleave weights --------------------------------- */
__global__ __launch_bounds__(256) void prep_kernel(
    const float* __restrict__ Wq, const float* __restrict__ Wk,
    const float* __restrict__ Wv)
{
    int idx = blockIdx.x * 256 + threadIdx.x;    /* 64*16*96 = 98304 */
    int c   = idx / (BKp * BNp);
    int rem = idx % (BKp * BNp);
    int kk  = rem / BNp;
    int col = rem % BNp;
    int k   = c * BKp + kk;

    float b;
    if      (col < 32) b = Wq[col * HIDDEN + k];
    else if (col < 64) b = Wk[(col - 32) * HIDDEN + k];
    else               b = Wv[(col - 64) * HIDDEN + k];

    int colgrp = col / 6;
    int j      = col % 6;
    g_B[c][kk][j * 16 + colgrp] = b;
}

/* ---------------- proj kernel: FFMA2 (f32x2) GEMM, 256 threads ------------- */
__global__ __launch_bounds__(256) void proj_kernel(
    const float* __restrict__ hmat,
    const float* __restrict__ Wg, const float* __restrict__ bg,
    const float* __restrict__ bq, const float* __restrict__ bk_,
    const float* __restrict__ bv)
{
    __shared__ float As[2][BKp][BMp + 2];   /* k-major, stride 130 (even) */
    __shared__ float Bs[2][BKp][BNp];       /* scalar, interleaved */
    __shared__ float Gs[2][BKp];

    const int tid    = threadIdx.x;
    const int colgrp = tid & 15;
    const int rowgrp = tid >> 4;            /* 0..15, 8 rows each */
    const long r0    = (long)blockIdx.x * BMp;

    unsigned long long acc[4][6];
    #pragma unroll
    for (int i = 0; i < 4; i++)
        #pragma unroll
        for (int j = 0; j < 6; j++) acc[i][j] = 0ull;
    float accg = 0.f;

    /* prologue: load chunk 0 into regs */
    float4 av[2];        /* A: 2048 floats / 256 thr = 2 float4 */
    float2 bvv[3];       /* B: 1536 floats / 256 thr = 3 float2 */
    float  gv;
    {
        #pragma unroll
        for (int q = 0; q < 2; q++) {
            int i   = tid + 256 * q;      /* 0..511 */
            int row = i >> 2;
            int kg  = (i & 3) * 4;
            av[q] = *(const float4*)(hmat + (r0 + row) * HIDDEN + kg);
        }
        const float2* bsrc = (const float2*)&g_B[0][0][0];
        #pragma unroll
        for (int q = 0; q < 3; q++) bvv[q] = bsrc[tid + 256 * q];
        gv = (tid < BKp) ? Wg[tid] : 0.f;
    }
    /* STS chunk 0 -> stage 0 */
    {
        #pragma unroll
        for (int q = 0; q < 2; q++) {
            int i   = tid + 256 * q;
            int row = i >> 2;
            int kg  = (i & 3) * 4;
            As[0][kg+0][row] = av[q].x;
            As[0][kg+1][row] = av[q].y;
            As[0][kg+2][row] = av[q].z;
            As[0][kg+3][row] = av[q].w;
        }
        float2* bdst = (float2*)&Bs[0][0][0];
        #pragma unroll
        for (int q = 0; q < 3; q++) bdst[tid + 256 * q] = bvv[q];
        if (tid < BKp) Gs[0][tid] = gv;
    }
    __syncthreads();

    for (int c = 0; c < NCHUNKS; c++) {
        const int s = c & 1;

        /* prefetch chunk c+1 into regs */
        if (c + 1 < NCHUNKS) {
            const int k0n = (c + 1) * BKp;
            #pragma unroll
            for (int q = 0; q < 2; q++) {
                int i   = tid + 256 * q;
                int row = i >> 2;
                int kg  = (i & 3) * 4;
                av[q] = *(const float4*)(hmat + (r0 + row) * HIDDEN + k0n + kg);
            }
            const float2* bsrc = (const float2*)&g_B[c + 1][0][0];
            #pragma unroll
            for (int q = 0; q < 3; q++) bvv[q] = bsrc[tid + 256 * q];
            gv = (tid < BKp) ? Wg[k0n + tid] : 0.f;
        }

        /* compute 16 kk from stage s */
        #pragma unroll
        for (int kk = 0; kk < BKp; kk++) {
            unsigned long long a[4], b[6];
            #pragma unroll
            for (int i = 0; i < 4; i++)
                a[i] = *(const unsigned long long*)&As[s][kk][rowgrp * 8 + 2 * i];
            #pragma unroll
            for (int j = 0; j < 6; j++)
                b[j] = dup2(Bs[s][kk][j * 16 + colgrp]);
            #pragma unroll
            for (int i = 0; i < 4; i++)
                #pragma unroll
                for (int j = 0; j < 6; j++)
                    ffma2(acc[i][j], a[i], b[j]);
            if (tid < 128) accg = fmaf(As[s][kk][tid], Gs[s][kk], accg);
        }

        /* store prefetched chunk to other stage */
        if (c + 1 < NCHUNKS) {
            const int sn = s ^ 1;
            #pragma unroll
            for (int q = 0; q < 2; q++) {
                int i   = tid + 256 * q;
                int row = i >> 2;
                int kg  = (i & 3) * 4;
                As[sn][kg+0][row] = av[q].x;
                As[sn][kg+1][row] = av[q].y;
                As[sn][kg+2][row] = av[q].z;
                As[sn][kg+3][row] = av[q].w;
            }
            float2* bdst = (float2*)&Bs[sn][0][0];
            #pragma unroll
            for (int q = 0; q < 3; q++) bdst[tid + 256 * q] = bvv[q];
            if (tid < BKp) Gs[sn][tid] = gv;
        }
        __syncthreads();
    }

    /* epilogue */
    const int C = colgrp * 6;
    float bias[6];
    #pragma unroll
    for (int j = 0; j < 6; j++) {
        int col = C + j;
        bias[j] = (col < 32) ? bq[col] : (col < 64) ? bk_[col - 32] : bv[col - 64];
    }
    #pragma unroll
    for (int i = 0; i < 4; i++) {
        long row0 = r0 + rowgrp * 8 + 2 * i;
        float v0[6], v1[6];
        #pragma unroll
        for (int j = 0; j < 6; j++) {
            v0[j] = f2lo(acc[i][j]) + bias[j];
            v1[j] = f2hi(acc[i][j]) + bias[j];
        }
        #pragma unroll
        for (int jj = 0; jj < 6; jj += 2) {
            int col = C + jj;
            float* dst;
            int cc;
            if      (col < 32) { dst = g_Q;  cc = col; }
            else if (col < 64) { dst = g_FK; cc = col - 32; }
            else               { dst = g_FV; cc = col - 64; }
            *(float2*)(dst + row0 * 32 + cc)       = make_float2(v0[jj], v0[jj+1]);
            *(float2*)(dst + (row0 + 1) * 32 + cc) = make_float2(v1[jj], v1[jj+1]);
        }
    }
    if (tid < 128) g_G[r0 + tid] = accg + bg[0];
}

/* ---------------- Kernel 2: recurrence, one warp per batch ----------------- */
#define NW 2

__global__ __launch_bounds__(32*NW) void rnn_kernel(float* __restrict__ es,
                                                    float* __restrict__ ps)
{
    __shared__ float Vs [NW][MEM][VAL+1];
    __shared__ float qs [NW][KEY];
    __shared__ float fks[NW][KEY];
    __shared__ float fvs[NW][VAL];
    __shared__ float ats[NW][MEM];

    const int w    = threadIdx.x >> 5;
    const int lane = threadIdx.x & 31;
    const int b    = blockIdx.x * NW + w;
    const unsigned FULL = 0xffffffffu;
    const float scale = 0.17677669529663688f;

    float K[KEY];
    #pragma unroll
    for (int j = 0; j < KEY; j++) { K[j] = 0.f; Vs[w][lane][j] = 0.f; }
    float Tf = 0.f, msk = 0.f;
    __syncwarp();

    const long row0 = (long)b * TLEN;
    float qv  = g_Q [row0*KEY + lane];
    float fkv = g_FK[row0*KEY + lane];
    float fvv = g_FV[row0*VAL + lane];
    float gx  = g_G [row0];

    for (int t = 0; t < TLEN; t++) {
        const long row  = row0 + t;
        const long nrow = (t < TLEN-1) ? row + 1 : row;

        float nq  = g_Q [nrow*KEY + lane];
        float nfk = g_FK[nrow*KEY + lane];
        float nfv = g_FV[nrow*VAL + lane];
        float ngx = g_G [nrow];

        qs [w][lane] = qv;
        fks[w][lane] = fkv;
        fvs[w][lane] = fvv;
        __syncwarp();

        float lg = 0.f;
        #pragma unroll
        for (int j = 0; j < KEY; j++) lg = fmaf(K[j], qs[w][j], lg);
        lg *= scale;
        float lm = fmaf(1.0f - msk, -1e9f, lg);

        unsigned ub  = __float_as_uint(lm);
        unsigned key = ub ^ ((unsigned)((int)ub >> 31) | 0x80000000u);
        unsigned km  = redux_umax(key);
        unsigned mb  = (km & 0x80000000u) ? (km ^ 0x80000000u) : ~km;
        float mx = __uint_as_float(mb);

        float ex = expf(lm - mx);
        float sm = ex;
        #pragma unroll
        for (int off = 16; off; off >>= 1)
            sm += __shfl_xor_sync(FULL, sm, off);
        float attn = ex / sm;
        ats[w][lane] = attn;

        unsigned ab = __float_as_uint(attn);
        unsigned am = redux_umax(ab);
        int amax = __ffs(__ballot_sync(FULL, ab == am)) - 1;
        __syncwarp();

        float r = 0.f;
        #pragma unroll
        for (int m = 0; m < MEM; m++)
            r = fmaf(ats[w][m], Vs[w][m][lane], r);

        unsigned bal = __ballot_sync(FULL, msk != 0.f);
        bool empty = (bal == 0u);
        bool warm  = (t < NWARMUP);
        float p = 1.f / (1.f + expf(-gx));
        float gate = (empty || warm) ? 0.f : p;
        bool wr = empty || warm || (gx < 0.f);

        float om = 1.0f - gate;
        float e  = gate * r + om * fvv;
        es[row*VAL + lane] = e;
        if (lane == 0) ps[row] = p;

        float evv = Tf + msk * 0.001f;
        unsigned eb = __float_as_uint(evv);
        unsigned em = redux_umin(eb);
        int evict = __ffs(__ballot_sync(FULL, eb == em)) - 1;

        if (wr && lane == evict) {
            msk = 1.f;
            #pragma unroll
            for (int j = 0; j < KEY; j++) {
                K[j] = fks[w][j];
                Vs[w][lane][j] = fvs[w][j];
            }
        }
        int bslot = wr ? evict : amax;
        float A = Tf * 0.85f;
        Tf = (lane == bslot) ? (A + (1.0f - A)) : A;
        __syncwarp();

        qv = nq; fkv = nfk; fvv = nfv; gx = ngx;
    }
}

/* ---------------- launch ---------------------------------------------------- */
extern "C" void kernel_launch(void* const* d_in, const int* in_sizes, int n_in,
                              void* d_out, int out_size)
{
    const float* h  = (const float*)d_in[0];
    const float* Wg = (const float*)d_in[1];
    const float* bg = (const float*)d_in[2];
    const float* Wq = (const float*)d_in[3];
    const float* bq = (const float*)d_in[4];
    const float* Wk = (const float*)d_in[5];
    const float* bk = (const float*)d_in[6];
    const float* Wv = (const float*)d_in[7];
    const float* bv = (const float*)d_in[8];

    float* es = (float*)d_out;
    float* ps = es + ((long)out_size - BT);

    prep_kernel<<<(NCHUNKS*BKp*BNp)/256, 256>>>(Wq, Wk, Wv);
    proj_kernel<<<BT/BMp, 256>>>(h, Wg, bg, bq, bk, bv);
    rnn_kernel<<<BATCH/NW, 32*NW>>>(es, ps);
}